// round 2
// baseline (speedup 1.0000x reference)
#include <cuda_runtime.h>
#include <math.h>

// ---------------------------------------------------------------------------
// SelfAttention: B=8, N=2048, D=512 (single head), fp32.
//   qkv = x @ w_qkv + b_qkv
//   S   = softmax(scale * Q K^T)
//   O   = S V
//   out = O @ w_fc + b_fc + x
// Round-2: same 5-launch fp32 pipeline, SGEMM now software-pipelined
// (register prefetch of the next K-tile overlaps LDG with the FFMA block).
// tcgen05 conversion deferred until a baseline bench + ncu confirm the
// fma-bound model and the rel-err headroom.
// ---------------------------------------------------------------------------

#define BM 128
#define BN 128
#define BK 16
#define TM 8
#define TN 8

static const int Bb = 8;
static const int Nn = 2048;
static const int Dd = 512;
static const int Mtot = Bb * Nn;       // 16384

// Scratch (static __device__ — no allocations allowed)
__device__ float g_qkv[16384ull * 1536];       // 100.7 MB
__device__ float g_s[8ull * 2048 * 2048];      // 134 MB
__device__ float g_o[16384ull * 512];          // 33.5 MB

// Generic tiled SGEMM: C = alpha * A @ B(^T) [+ bias] [+ residual]
// A: [M,K] row-major (lda), B: [K,N] row-major (ldb) or [N,K] if TRANS_B.
// All of M, N divisible by 128 and K divisible by 16 in every use below,
// so no bounds checks. Global->register prefetch double-buffers the K loop.
template<bool TRANS_B, bool HAS_BIAS, bool HAS_RES>
__global__ __launch_bounds__(256, 2)
void sgemm128(const float* __restrict__ A, const float* __restrict__ B,
              float* __restrict__ C, int K,
              int lda, int ldb, int ldc,
              long sA, long sB, long sC,
              float alpha,
              const float* __restrict__ bias,
              const float* __restrict__ res, int ldres)
{
    A += (long)blockIdx.z * sA;
    B += (long)blockIdx.z * sB;
    C += (long)blockIdx.z * sC;

    __shared__ float As[BK][BM];
    __shared__ float Bs[BK][BN];

    const int tid = threadIdx.x;
    const int tx = tid & 15;         // 16 thread-cols
    const int ty = tid >> 4;         // 16 thread-rows
    const int m0 = blockIdx.y * BM;
    const int n0 = blockIdx.x * BN;

    // Per-thread tile-load coordinates (2 float4 each for A and B).
    // A tile (and TRANS_B B tile): idx = tid + it*256 in 0..511,
    //   r = idx>>2 (0..127), c = (idx&3)<<2 (0,4,8,12)
    // Non-trans B tile: r = idx>>5 (0..15), c = (idx&31)<<2 (0..124)
    const int arA[2] = { (tid + 0)   >> 2, (tid + 256) >> 2 };
    const int acA[2] = { ((tid + 0) & 3) << 2, ((tid + 256) & 3) << 2 };
    const int brN[2] = { (tid + 0)   >> 5, (tid + 256) >> 5 };
    const int bcN[2] = { ((tid + 0) & 31) << 2, ((tid + 256) & 31) << 2 };

    float acc[TM][TN];
#pragma unroll
    for (int i = 0; i < TM; ++i)
#pragma unroll
        for (int j = 0; j < TN; ++j) acc[i][j] = 0.0f;

    float4 pa[2], pb[2];

    // --- prologue: prefetch first tiles into registers ---
#pragma unroll
    for (int it = 0; it < 2; ++it)
        pa[it] = *reinterpret_cast<const float4*>(
            &A[(long)(m0 + arA[it]) * lda + acA[it]]);
    if (TRANS_B) {
#pragma unroll
        for (int it = 0; it < 2; ++it)
            pb[it] = *reinterpret_cast<const float4*>(
                &B[(long)(n0 + arA[it]) * ldb + acA[it]]);
    } else {
#pragma unroll
        for (int it = 0; it < 2; ++it)
            pb[it] = *reinterpret_cast<const float4*>(
                &B[(long)brN[it] * ldb + n0 + bcN[it]]);
    }

    for (int k0 = 0; k0 < K; k0 += BK) {
        // --- stage prefetched tiles into smem ---
#pragma unroll
        for (int it = 0; it < 2; ++it) {
            int r = arA[it], c = acA[it];
            As[c + 0][r] = pa[it].x; As[c + 1][r] = pa[it].y;
            As[c + 2][r] = pa[it].z; As[c + 3][r] = pa[it].w;
        }
        if (TRANS_B) {
#pragma unroll
            for (int it = 0; it < 2; ++it) {
                int r = arA[it], c = acA[it];
                Bs[c + 0][r] = pb[it].x; Bs[c + 1][r] = pb[it].y;
                Bs[c + 2][r] = pb[it].z; Bs[c + 3][r] = pb[it].w;
            }
        } else {
#pragma unroll
            for (int it = 0; it < 2; ++it)
                *reinterpret_cast<float4*>(&Bs[brN[it]][bcN[it]]) = pb[it];
        }
        __syncthreads();

        // --- prefetch next tiles (overlaps with the FFMA block below) ---
        const int k1 = k0 + BK;
        if (k1 < K) {
#pragma unroll
            for (int it = 0; it < 2; ++it)
                pa[it] = *reinterpret_cast<const float4*>(
                    &A[(long)(m0 + arA[it]) * lda + k1 + acA[it]]);
            if (TRANS_B) {
#pragma unroll
                for (int it = 0; it < 2; ++it)
                    pb[it] = *reinterpret_cast<const float4*>(
                        &B[(long)(n0 + arA[it]) * ldb + k1 + acA[it]]);
            } else {
#pragma unroll
                for (int it = 0; it < 2; ++it)
                    pb[it] = *reinterpret_cast<const float4*>(
                        &B[(long)(k1 + brN[it]) * ldb + n0 + bcN[it]]);
            }
        }

        // --- compute on the staged tiles ---
#pragma unroll
        for (int k = 0; k < BK; ++k) {
            float ra[TM], rb[TN];
            float4 a0 = *reinterpret_cast<const float4*>(&As[k][ty * TM]);
            float4 a1 = *reinterpret_cast<const float4*>(&As[k][ty * TM + 4]);
            ra[0] = a0.x; ra[1] = a0.y; ra[2] = a0.z; ra[3] = a0.w;
            ra[4] = a1.x; ra[5] = a1.y; ra[6] = a1.z; ra[7] = a1.w;
            float4 b0 = *reinterpret_cast<const float4*>(&Bs[k][tx * TN]);
            float4 b1 = *reinterpret_cast<const float4*>(&Bs[k][tx * TN + 4]);
            rb[0] = b0.x; rb[1] = b0.y; rb[2] = b0.z; rb[3] = b0.w;
            rb[4] = b1.x; rb[5] = b1.y; rb[6] = b1.z; rb[7] = b1.w;
#pragma unroll
            for (int i = 0; i < TM; ++i)
#pragma unroll
                for (int j = 0; j < TN; ++j)
                    acc[i][j] = fmaf(ra[i], rb[j], acc[i][j]);
        }
        __syncthreads();
    }

    // --- epilogue: scale, bias, residual, vectorized store ---
#pragma unroll
    for (int i = 0; i < TM; ++i) {
        int row = m0 + ty * TM + i;
#pragma unroll
        for (int j4 = 0; j4 < TN; j4 += 4) {
            int col = n0 + tx * TN + j4;
            float4 v;
            v.x = acc[i][j4 + 0] * alpha;
            v.y = acc[i][j4 + 1] * alpha;
            v.z = acc[i][j4 + 2] * alpha;
            v.w = acc[i][j4 + 3] * alpha;
            if (HAS_BIAS) {
                v.x += bias[col + 0]; v.y += bias[col + 1];
                v.z += bias[col + 2]; v.w += bias[col + 3];
            }
            if (HAS_RES) {
                float4 r = *reinterpret_cast<const float4*>(
                    &res[(long)row * ldres + col]);
                v.x += r.x; v.y += r.y; v.z += r.z; v.w += r.w;
            }
            *reinterpret_cast<float4*>(&C[(long)row * ldc + col]) = v;
        }
    }
}

// Row softmax over 2048 columns, one CTA per row, 256 threads x 8 elems.
__global__ __launch_bounds__(256)
void softmax2048(float* __restrict__ S)
{
    float* row = S + (long)blockIdx.x * 2048;
    const int t = threadIdx.x;
    __shared__ float red[8];

    float v[8];
    float m = -1e30f;
#pragma unroll
    for (int r = 0; r < 8; ++r) {
        v[r] = row[t + r * 256];
        m = fmaxf(m, v[r]);
    }
#pragma unroll
    for (int o = 16; o > 0; o >>= 1)
        m = fmaxf(m, __shfl_xor_sync(0xFFFFFFFFu, m, o));
    if ((t & 31) == 0) red[t >> 5] = m;
    __syncthreads();
    float mAll = red[0];
#pragma unroll
    for (int w = 1; w < 8; ++w) mAll = fmaxf(mAll, red[w]);
    __syncthreads();

    float s = 0.0f;
#pragma unroll
    for (int r = 0; r < 8; ++r) {
        v[r] = __expf(v[r] - mAll);
        s += v[r];
    }
#pragma unroll
    for (int o = 16; o > 0; o >>= 1)
        s += __shfl_xor_sync(0xFFFFFFFFu, s, o);
    if ((t & 31) == 0) red[t >> 5] = s;
    __syncthreads();
    float tot = 0.0f;
#pragma unroll
    for (int w = 0; w < 8; ++w) tot += red[w];
    float inv = 1.0f / tot;
#pragma unroll
    for (int r = 0; r < 8; ++r)
        row[t + r * 256] = v[r] * inv;
}

extern "C" void kernel_launch(void* const* d_in, const int* in_sizes, int n_in,
                              void* d_out, int out_size)
{
    const float* x     = (const float*)d_in[0];  // [8,2048,512]
    const float* w_qkv = (const float*)d_in[1];  // [512,1536]
    const float* b_qkv = (const float*)d_in[2];  // [1536]
    const float* w_fc  = (const float*)d_in[3];  // [512,512]
    const float* b_fc  = (const float*)d_in[4];  // [512]
    float* out = (float*)d_out;                  // [8,2048,512]

    float *qkv, *s, *o;
    cudaGetSymbolAddress((void**)&qkv, g_qkv);
    cudaGetSymbolAddress((void**)&s,   g_s);
    cudaGetSymbolAddress((void**)&o,   g_o);

    const float scale = 1.0f / sqrtf((float)Dd);

    // 1) qkv[16384,1536] = x[16384,512] @ w_qkv[512,1536] + b_qkv
    sgemm128<false, true, false><<<dim3(1536 / BN, Mtot / BM, 1), 256>>>(
        x, w_qkv, qkv, Dd,
        Dd, 1536, 1536,
        0, 0, 0,
        1.0f, b_qkv, nullptr, 0);

    // 2) S[b] = scale * Q[b] @ K[b]^T   (Q at col 0, K at col 512 of qkv)
    sgemm128<true, false, false><<<dim3(Nn / BN, Nn / BM, Bb), 256>>>(
        qkv + 0, qkv + 512, s, Dd,
        1536, 1536, Nn,
        (long)Nn * 1536, (long)Nn * 1536, (long)Nn * Nn,
        scale, nullptr, nullptr, 0);

    // 3) softmax over each of the 8*2048 rows
    softmax2048<<<Bb * Nn, 256>>>(s);

    // 4) O[b] = S[b] @ V[b]   (V at col 1024 of qkv)
    sgemm128<false, false, false><<<dim3(Dd / BN, Nn / BM, Bb), 256>>>(
        s, qkv + 1024, o, Nn,
        Nn, 1536, Dd,
        (long)Nn * Nn, (long)Nn * 1536, (long)Nn * Dd,
        1.0f, nullptr, nullptr, 0);

    // 5) out = O @ w_fc + b_fc + x
    sgemm128<false, true, true><<<dim3(Dd / BN, Mtot / BM, 1), 256>>>(
        o, w_fc, out, Dd,
        Dd, Dd, Dd,
        0, 0, 0,
        1.0f, b_fc, x, Dd);
}

// round 17
// speedup vs baseline: 1.6500x; 1.6500x over previous
#include <cuda_runtime.h>
#include <cuda_bf16.h>
#include <cstdint>
#include <math.h>

// ---------------------------------------------------------------------------
// SelfAttention B=8, N=2048, D=512 fp32.
// GEMMs via arch-agnostic mma.sync.m16n8k16 bf16 (HMMA) with hi/lo split:
//   C = Ahi*Bhi + Ahi*Blo + Alo*Bhi   (fp32 register accumulation)
// (tcgen05 is unavailable: harness generates compute_103 PTX, which rejects
//  all sm_103a-specific features — confirmed by round-13 ptxas errors.)
// All four GEMMs are NT: A [M,K], B [N,K], K-major. 128x128x32 CTA tiles,
// 8 warps x (32x64) warp tiles, padded smem, register-prefetch pipeline.
// ---------------------------------------------------------------------------

typedef __nv_bfloat16 bf16;

constexpr int Bb = 8, Nn = 2048, Dd = 512, Mtot = 16384;

// ============================ device scratch ===============================
__device__ bf16  g_xhi[16384ll * 512],  g_xlo[16384ll * 512];
__device__ bf16  g_wqT_hi[1536 * 512],  g_wqT_lo[1536 * 512];
__device__ bf16  g_wfT_hi[512 * 512],   g_wfT_lo[512 * 512];
__device__ float g_qkv[16384ll * 1536];
__device__ bf16  g_qhi[16384ll * 512],  g_qlo[16384ll * 512];
__device__ bf16  g_khi[16384ll * 512],  g_klo[16384ll * 512];
__device__ bf16  g_vthi[8ll * 512 * 2048], g_vtlo[8ll * 512 * 2048];
__device__ float g_s[8ll * 2048 * 2048];
__device__ bf16  g_shi[8ll * 2048 * 2048], g_slo[8ll * 2048 * 2048];
__device__ float g_o[16384ll * 512];
__device__ bf16  g_ohi[16384ll * 512],  g_olo[16384ll * 512];

__device__ __forceinline__ void split1(float x, bf16& h, bf16& l) {
    h = __float2bfloat16(x);
    l = __float2bfloat16(x - __bfloat162float(h));
}

// mma.sync m16n8k16 row.col bf16 -> f32 (arch-agnostic, sm_80+)
__device__ __forceinline__ void mma16816(float* c, const uint32_t* a,
                                         const uint32_t* b) {
    asm volatile(
        "mma.sync.aligned.m16n8k16.row.col.f32.bf16.bf16.f32 "
        "{%0,%1,%2,%3}, {%4,%5,%6,%7}, {%8,%9}, {%0,%1,%2,%3};"
        : "+f"(c[0]), "+f"(c[1]), "+f"(c[2]), "+f"(c[3])
        : "r"(a[0]), "r"(a[1]), "r"(a[2]), "r"(a[3]),
          "r"(b[0]), "r"(b[1]));
}

// =============================== MMA GEMM ==================================
// D[M,N] = alpha*(Ahi+Alo)(Bhi+Blo)^T (+bias)(+res); BM=BN=128, BK=32.
// 8 warps as 4(m) x 2(n); warp tile 32x64 = 2 x 8 m16n8k16 atoms.
// smem pitch 40 bf16 (20 b32 words) -> conflict-free fragment loads.
#define SPITCH 40
#define SPITCH32 20

template<bool HAS_BIAS, bool HAS_RES>
__global__ void __launch_bounds__(256, 2)
mma_gemm(const bf16* __restrict__ Ahi, const bf16* __restrict__ Alo,
         const bf16* __restrict__ Bhi, const bf16* __restrict__ Blo,
         float* __restrict__ C, int K, int lda, int ldb, int ldc,
         long sA, long sB, long sC, float alpha,
         const float* __restrict__ bias, const float* __restrict__ res)
{
    __shared__ bf16 As[128][SPITCH];
    __shared__ bf16 Bs[128][SPITCH];

    const int tid = threadIdx.x, wid = tid >> 5, lid = tid & 31;
    const int wm = wid & 3, wn = wid >> 2;       // 4x2 warp grid
    const int g = lid >> 2, t = lid & 3;         // fragment lane coords
    const int z = blockIdx.z;
    const long m0 = (long)blockIdx.y * 128;
    const long n0 = (long)blockIdx.x * 128;
    Ahi += z * sA; Alo += z * sA;
    Bhi += z * sB; Blo += z * sB;
    C   += z * sC;

    const uint32_t* As32 = reinterpret_cast<const uint32_t*>(&As[0][0]);
    const uint32_t* Bs32 = reinterpret_cast<const uint32_t*>(&Bs[0][0]);

    float acc[2][8][4];
#pragma unroll
    for (int ma = 0; ma < 2; ++ma)
#pragma unroll
        for (int na = 0; na < 8; ++na)
#pragma unroll
            for (int f = 0; f < 4; ++f) acc[ma][na][f] = 0.0f;

    // per-thread staging coords: idx = tid + i*256 in 0..511
    //   row = idx>>2 (0..127), coff = (idx&3)*8  (8 bf16 = 16B)
    const int srow[2] = { (tid + 0) >> 2, (tid + 256) >> 2 };
    const int scol[2] = { ((tid + 0) & 3) * 8, ((tid + 256) & 3) * 8 };

    const int nk = K >> 5;               // chunks of BK=32
    const int total = 3 * nk;            // 3 hi/lo phases

    uint4 pa[2], pb[2];
    {   // prologue: prefetch chunk 0 (phase 0: Ahi x Bhi)
#pragma unroll
        for (int i = 0; i < 2; ++i) {
            pa[i] = *reinterpret_cast<const uint4*>(
                Ahi + (m0 + srow[i]) * lda + scol[i]);
            pb[i] = *reinterpret_cast<const uint4*>(
                Bhi + (n0 + srow[i]) * ldb + scol[i]);
        }
    }

#pragma unroll 1
    for (int c = 0; c < total; ++c) {
        // stage prefetched tiles into smem
#pragma unroll
        for (int i = 0; i < 2; ++i) {
            *reinterpret_cast<uint4*>(&As[srow[i]][scol[i]]) = pa[i];
            *reinterpret_cast<uint4*>(&Bs[srow[i]][scol[i]]) = pb[i];
        }
        __syncthreads();

        // prefetch next chunk (overlaps with MMA block)
        if (c + 1 < total) {
            const int c2 = c + 1;
            const int p2 = c2 / nk, kc2 = c2 - p2 * nk;
            const bf16* Ap = (p2 == 2) ? Alo : Ahi;
            const bf16* Bp = (p2 == 1) ? Blo : Bhi;
            const long k0 = (long)kc2 << 5;
#pragma unroll
            for (int i = 0; i < 2; ++i) {
                pa[i] = *reinterpret_cast<const uint4*>(
                    Ap + (m0 + srow[i]) * lda + k0 + scol[i]);
                pb[i] = *reinterpret_cast<const uint4*>(
                    Bp + (n0 + srow[i]) * ldb + k0 + scol[i]);
            }
        }

        // compute: 2 k16 steps on the staged 128x32 tiles
#pragma unroll
        for (int k16 = 0; k16 < 2; ++k16) {
            const int kb = k16 * 8;      // b32 offset within row
            uint32_t af[2][4];
#pragma unroll
            for (int ma = 0; ma < 2; ++ma) {
                const int ra = wm * 32 + ma * 16 + g;
                af[ma][0] = As32[(ra    ) * SPITCH32 + kb + t];
                af[ma][1] = As32[(ra + 8) * SPITCH32 + kb + t];
                af[ma][2] = As32[(ra    ) * SPITCH32 + kb + 4 + t];
                af[ma][3] = As32[(ra + 8) * SPITCH32 + kb + 4 + t];
            }
#pragma unroll
            for (int na = 0; na < 8; ++na) {
                const int rb = wn * 64 + na * 8 + g;
                uint32_t bf[2];
                bf[0] = Bs32[rb * SPITCH32 + kb + t];
                bf[1] = Bs32[rb * SPITCH32 + kb + 4 + t];
#pragma unroll
                for (int ma = 0; ma < 2; ++ma)
                    mma16816(acc[ma][na], af[ma], bf);
            }
        }
        __syncthreads();
    }

    // epilogue: c0,c1 -> (row g, cols 2t,2t+1); c2,c3 -> (row g+8)
#pragma unroll
    for (int ma = 0; ma < 2; ++ma) {
#pragma unroll
        for (int na = 0; na < 8; ++na) {
            const long row0 = m0 + wm * 32 + ma * 16 + g;
            const long row1 = row0 + 8;
            const long col  = n0 + wn * 64 + na * 8 + t * 2;
            float2 v0, v1;
            v0.x = acc[ma][na][0] * alpha; v0.y = acc[ma][na][1] * alpha;
            v1.x = acc[ma][na][2] * alpha; v1.y = acc[ma][na][3] * alpha;
            if (HAS_BIAS) {
                const float b0 = bias[col], b1 = bias[col + 1];
                v0.x += b0; v0.y += b1; v1.x += b0; v1.y += b1;
            }
            if (HAS_RES) {
                float2 r0 = *reinterpret_cast<const float2*>(
                    res + row0 * ldc + col);
                float2 r1 = *reinterpret_cast<const float2*>(
                    res + row1 * ldc + col);
                v0.x += r0.x; v0.y += r0.y; v1.x += r1.x; v1.y += r1.y;
            }
            *reinterpret_cast<float2*>(C + row0 * ldc + col) = v0;
            *reinterpret_cast<float2*>(C + row1 * ldc + col) = v1;
        }
    }
}

// =========================== conversion kernels ============================
__global__ void __launch_bounds__(256)
split_f32(const float* __restrict__ in, bf16* __restrict__ hi,
          bf16* __restrict__ lo)
{
    long i = ((long)blockIdx.x * 256 + threadIdx.x) * 4;
    float4 v = *reinterpret_cast<const float4*>(in + i);
    bf16 h[4], l[4];
    split1(v.x, h[0], l[0]); split1(v.y, h[1], l[1]);
    split1(v.z, h[2], l[2]); split1(v.w, h[3], l[3]);
    *reinterpret_cast<__nv_bfloat162*>(hi + i)     = __nv_bfloat162(h[0], h[1]);
    *reinterpret_cast<__nv_bfloat162*>(hi + i + 2) = __nv_bfloat162(h[2], h[3]);
    *reinterpret_cast<__nv_bfloat162*>(lo + i)     = __nv_bfloat162(l[0], l[1]);
    *reinterpret_cast<__nv_bfloat162*>(lo + i + 2) = __nv_bfloat162(l[2], l[3]);
}

// Q/K extraction from qkv [16384,1536] -> [16384,512] splits
__global__ void __launch_bounds__(256)
split_qk(const float* __restrict__ qkv)
{
    long gidx = (long)blockIdx.x * 256 + threadIdx.x;
    long row = gidx >> 7;
    long c = (gidx & 127) * 4;
    float4 q = *reinterpret_cast<const float4*>(qkv + row * 1536 + c);
    float4 k = *reinterpret_cast<const float4*>(qkv + row * 1536 + 512 + c);
    bf16 h[4], l[4];
    long o = row * 512 + c;
    split1(q.x, h[0], l[0]); split1(q.y, h[1], l[1]);
    split1(q.z, h[2], l[2]); split1(q.w, h[3], l[3]);
    *reinterpret_cast<__nv_bfloat162*>(g_qhi + o)     = __nv_bfloat162(h[0], h[1]);
    *reinterpret_cast<__nv_bfloat162*>(g_qhi + o + 2) = __nv_bfloat162(h[2], h[3]);
    *reinterpret_cast<__nv_bfloat162*>(g_qlo + o)     = __nv_bfloat162(l[0], l[1]);
    *reinterpret_cast<__nv_bfloat162*>(g_qlo + o + 2) = __nv_bfloat162(l[2], l[3]);
    split1(k.x, h[0], l[0]); split1(k.y, h[1], l[1]);
    split1(k.z, h[2], l[2]); split1(k.w, h[3], l[3]);
    *reinterpret_cast<__nv_bfloat162*>(g_khi + o)     = __nv_bfloat162(h[0], h[1]);
    *reinterpret_cast<__nv_bfloat162*>(g_khi + o + 2) = __nv_bfloat162(h[2], h[3]);
    *reinterpret_cast<__nv_bfloat162*>(g_klo + o)     = __nv_bfloat162(l[0], l[1]);
    *reinterpret_cast<__nv_bfloat162*>(g_klo + o + 2) = __nv_bfloat162(l[2], l[3]);
}

// Transpose+split generic: in [R,C] fp32 -> outT [C,R] bf16 hi/lo
__global__ void __launch_bounds__(256)
tsplit(const float* __restrict__ in, bf16* __restrict__ hiT,
       bf16* __restrict__ loT, int R, int C)
{
    __shared__ float tbuf[32][33];
    int c0 = blockIdx.x * 32, r0 = blockIdx.y * 32;
    int tx = threadIdx.x & 31, ty = threadIdx.x >> 5;
#pragma unroll
    for (int i = 0; i < 4; ++i)
        tbuf[ty + i * 8][tx] = in[(long)(r0 + ty + i * 8) * C + c0 + tx];
    __syncthreads();
#pragma unroll
    for (int i = 0; i < 4; ++i) {
        int cy = ty + i * 8;
        bf16 h, l;
        split1(tbuf[tx][cy], h, l);
        hiT[(long)(c0 + cy) * R + r0 + tx] = h;
        loT[(long)(c0 + cy) * R + r0 + tx] = l;
    }
}

// V extraction + transpose + split: qkv[.,1024+d] per batch -> VT[b][d][n]
__global__ void __launch_bounds__(256)
tsplit_v(const float* __restrict__ qkv)
{
    __shared__ float tbuf[32][33];
    int d0 = blockIdx.x * 32, n0 = blockIdx.y * 32, z = blockIdx.z;
    int tx = threadIdx.x & 31, ty = threadIdx.x >> 5;
#pragma unroll
    for (int i = 0; i < 4; ++i)
        tbuf[ty + i * 8][tx] =
            qkv[((long)z * 2048 + n0 + ty + i * 8) * 1536 + 1024 + d0 + tx];
    __syncthreads();
#pragma unroll
    for (int i = 0; i < 4; ++i) {
        int dy = ty + i * 8;
        bf16 h, l;
        split1(tbuf[tx][dy], h, l);
        long o = (long)z * 512 * 2048 + (long)(d0 + dy) * 2048 + n0 + tx;
        g_vthi[o] = h;
        g_vtlo[o] = l;
    }
}

// Row softmax over 2048 cols, fused bf16 hi/lo split output.
__global__ void __launch_bounds__(256)
softmax_split(const float* __restrict__ S, bf16* __restrict__ Hi,
              bf16* __restrict__ Lo)
{
    const float* row = S + (long)blockIdx.x * 2048;
    const int t = threadIdx.x;
    __shared__ float red[8];
    float v[8];
    float m = -1e30f;
#pragma unroll
    for (int r = 0; r < 8; ++r) { v[r] = row[t + r * 256]; m = fmaxf(m, v[r]); }
#pragma unroll
    for (int o = 16; o > 0; o >>= 1)
        m = fmaxf(m, __shfl_xor_sync(0xFFFFFFFFu, m, o));
    if ((t & 31) == 0) red[t >> 5] = m;
    __syncthreads();
    float mA = red[0];
#pragma unroll
    for (int w = 1; w < 8; ++w) mA = fmaxf(mA, red[w]);
    __syncthreads();
    float s = 0.0f;
#pragma unroll
    for (int r = 0; r < 8; ++r) { v[r] = __expf(v[r] - mA); s += v[r]; }
#pragma unroll
    for (int o = 16; o > 0; o >>= 1) s += __shfl_xor_sync(0xFFFFFFFFu, s, o);
    if ((t & 31) == 0) red[t >> 5] = s;
    __syncthreads();
    float tot = 0.0f;
#pragma unroll
    for (int w = 0; w < 8; ++w) tot += red[w];
    float inv = 1.0f / tot;
    long base = (long)blockIdx.x * 2048;
#pragma unroll
    for (int r = 0; r < 8; ++r) {
        bf16 h, l;
        split1(v[r] * inv, h, l);
        Hi[base + t + r * 256] = h;
        Lo[base + t + r * 256] = l;
    }
}

// ================================ launch ===================================
extern "C" void kernel_launch(void* const* d_in, const int* in_sizes, int n_in,
                              void* d_out, int out_size)
{
    const float* x     = (const float*)d_in[0];
    const float* w_qkv = (const float*)d_in[1];
    const float* b_qkv = (const float*)d_in[2];
    const float* w_fc  = (const float*)d_in[3];
    const float* b_fc  = (const float*)d_in[4];
    float* out = (float*)d_out;

    bf16 *xhi, *xlo, *wqh, *wql, *wfh, *wfl, *qhi, *qlo, *khi, *klo;
    bf16 *vth, *vtl, *shi, *slo, *ohi, *olo;
    float *qkv, *s, *o;
    cudaGetSymbolAddress((void**)&xhi, g_xhi);  cudaGetSymbolAddress((void**)&xlo, g_xlo);
    cudaGetSymbolAddress((void**)&wqh, g_wqT_hi); cudaGetSymbolAddress((void**)&wql, g_wqT_lo);
    cudaGetSymbolAddress((void**)&wfh, g_wfT_hi); cudaGetSymbolAddress((void**)&wfl, g_wfT_lo);
    cudaGetSymbolAddress((void**)&qhi, g_qhi);  cudaGetSymbolAddress((void**)&qlo, g_qlo);
    cudaGetSymbolAddress((void**)&khi, g_khi);  cudaGetSymbolAddress((void**)&klo, g_klo);
    cudaGetSymbolAddress((void**)&vth, g_vthi); cudaGetSymbolAddress((void**)&vtl, g_vtlo);
    cudaGetSymbolAddress((void**)&shi, g_shi);  cudaGetSymbolAddress((void**)&slo, g_slo);
    cudaGetSymbolAddress((void**)&ohi, g_ohi);  cudaGetSymbolAddress((void**)&olo, g_olo);
    cudaGetSymbolAddress((void**)&qkv, g_qkv);
    cudaGetSymbolAddress((void**)&s,   g_s);
    cudaGetSymbolAddress((void**)&o,   g_o);

    const float scale = 1.0f / sqrtf((float)Dd);

    // 0) splits of x and weights (weights transposed to [N,K])
    split_f32<<<(Mtot * Dd) / 1024, 256>>>(x, xhi, xlo);
    tsplit<<<dim3(1536 / 32, 512 / 32), 256>>>(w_qkv, wqh, wql, 512, 1536);
    tsplit<<<dim3(512 / 32, 512 / 32), 256>>>(w_fc, wfh, wfl, 512, 512);

    // 1) qkv = x @ w_qkv + b_qkv     [16384,1536]
    mma_gemm<true, false><<<dim3(1536 / 128, Mtot / 128, 1), 256>>>(
        xhi, xlo, wqh, wql, qkv, 512, 512, 512, 1536,
        0, 0, 0, 1.0f, b_qkv, nullptr);

    // 2) Q/K/V splits
    split_qk<<<(Mtot * 128) / 256, 256>>>(qkv);
    tsplit_v<<<dim3(512 / 32, 2048 / 32, 8), 256>>>(qkv);

    // 3) S = scale * Q K^T           [8][2048,2048]
    mma_gemm<false, false><<<dim3(2048 / 128, 2048 / 128, 8), 256>>>(
        qhi, qlo, khi, klo, s, 512, 512, 512, 2048,
        2048ll * 512, 2048ll * 512, 2048ll * 2048, scale, nullptr, nullptr);

    // 4) softmax + split
    softmax_split<<<Bb * Nn, 256>>>(s, shi, slo);

    // 5) O = S V                     [8][2048,512]
    mma_gemm<false, false><<<dim3(512 / 128, 2048 / 128, 8), 256>>>(
        shi, slo, vth, vtl, o, 2048, 2048, 2048, 512,
        2048ll * 2048, 512ll * 2048, 2048ll * 512, 1.0f, nullptr, nullptr);

    // 6) split O
    split_f32<<<(Mtot * Dd) / 1024, 256>>>(o, ohi, olo);

    // 7) out = O @ w_fc + b_fc + x
    mma_gemm<true, true><<<dim3(512 / 128, Mtot / 128, 1), 256>>>(
        ohi, olo, wfh, wfl, out, 512, 512, 512, 512,
        0, 0, 0, 1.0f, b_fc, x);
}